// round 12
// baseline (speedup 1.0000x reference)
#include <cuda_runtime.h>
#include <math.h>

// ---------------------------------------------------------------------------
// ConditionalNormalizingFlow: L=6 RealNVP coupling layers.
//   B=32768, T_DIM=64 (HALF=32), COND=128, HID=1024.
// Per layer: params = MLP(concat(unmasked, cond)) ; s=tanh(p[:32]); t=p[32:]
//            z[masked] = z[masked]*exp(s) + t ; logdet += sum(s)
// Output: z [B,64] then log_det [B] (float32), concatenated in d_out.
// ---------------------------------------------------------------------------

#define BN_ 32768
#define TDIM 64
#define HALF_ 32
#define CONDD 128
#define HIDD 1024
#define KIN 160   // HALF + COND

// Scratch (device globals: allocation-free per harness rules)
__device__ float g_U [ (size_t)BN_ * KIN  ];   // 21 MB
__device__ float g_H1[ (size_t)BN_ * HIDD ];   // 128 MB
__device__ float g_H2[ (size_t)BN_ * HIDD ];   // 128 MB

// ---- packed f32x2 helpers (Blackwell FFMA2 path) --------------------------
__device__ __forceinline__ unsigned long long pk2(float x, float y) {
    unsigned long long r;
    asm("mov.b64 %0, {%1, %2};" : "=l"(r)
        : "r"(__float_as_uint(x)), "r"(__float_as_uint(y)));
    return r;
}
__device__ __forceinline__ float2 upk2(unsigned long long v) {
    unsigned int lo, hi;
    asm("mov.b64 {%0, %1}, %2;" : "=r"(lo), "=r"(hi) : "l"(v));
    return make_float2(__uint_as_float(lo), __uint_as_float(hi));
}
__device__ __forceinline__ unsigned long long ffma2(unsigned long long a,
                                                    unsigned long long b,
                                                    unsigned long long c) {
    unsigned long long d;
    asm("fma.rn.f32x2 %0, %1, %2, %3;" : "=l"(d) : "l"(a), "l"(b), "l"(c));
    return d;
}

// ---------------------------------------------------------------------------
// init: z = T, logdet = 0
// ---------------------------------------------------------------------------
__global__ void init_kernel(const float* __restrict__ T, float* __restrict__ out) {
    int i = blockIdx.x * 256 + threadIdx.x;
    if (i < BN_ * TDIM) out[i] = T[i];
    if (i < BN_)        out[(size_t)BN_ * TDIM + i] = 0.f;
}

// ---------------------------------------------------------------------------
// build U = concat(unmasked(z), cond)  -> [B, 160]
// uoff: offset of the unmasked half inside z row (32 for even layers, 0 odd)
// ---------------------------------------------------------------------------
__global__ void build_u_kernel(const float* __restrict__ z,
                               const float* __restrict__ cond,
                               float* __restrict__ U, int uoff) {
    int i = blockIdx.x * 256 + threadIdx.x;
    if (i >= BN_ * KIN) return;
    int b = i / KIN;
    int k = i - b * KIN;
    U[i] = (k < HALF_) ? z[(size_t)b * TDIM + uoff + k]
                       : cond[(size_t)b * CONDD + (k - HALF_)];
}

// ---------------------------------------------------------------------------
// C[M,1024] = relu(A[M,K] @ W[K,1024] + bias)     M=32768, K in {160,1024}
// Tiles: 128x128x16, 256 threads, 8x8 per-thread tile, f32x2 FMA.
// ---------------------------------------------------------------------------
__global__ __launch_bounds__(256, 2)
void gemm_relu_kernel(const float* __restrict__ A, int lda, int K,
                      const float* __restrict__ W,
                      const float* __restrict__ bias,
                      float* __restrict__ C) {
    __shared__ float As[16 * 132];
    __shared__ float Ws[16 * 132];

    const int tid = threadIdx.x;
    const int tx  = tid & 15;   // 16 groups x 8 cols = 128
    const int ty  = tid >> 4;   // 16 groups x 8 rows = 128
    const int m0  = blockIdx.y * 128;
    const int n0  = blockIdx.x * 128;

    unsigned long long acc[8][4];
#pragma unroll
    for (int i = 0; i < 8; i++)
#pragma unroll
        for (int j = 0; j < 4; j++) acc[i][j] = 0ull;

    for (int k0 = 0; k0 < K; k0 += 16) {
        // load A tile 128x16 (float4 along K, store transposed [k][m])
#pragma unroll
        for (int l = 0; l < 2; l++) {
            int idx = tid + l * 256;      // 0..511 float4 slots
            int m   = idx >> 2;           // 0..127
            int kk  = (idx & 3) << 2;     // 0,4,8,12
            const float4 v = *reinterpret_cast<const float4*>(
                A + (size_t)(m0 + m) * lda + k0 + kk);
            As[(kk + 0) * 132 + m] = v.x;
            As[(kk + 1) * 132 + m] = v.y;
            As[(kk + 2) * 132 + m] = v.z;
            As[(kk + 3) * 132 + m] = v.w;
        }
        // load W tile 16x128 (row-major, coalesced float4 along N)
#pragma unroll
        for (int l = 0; l < 2; l++) {
            int idx = tid + l * 256;
            int k   = idx >> 5;           // 0..15
            int n4  = (idx & 31) << 2;    // 0..124
            *reinterpret_cast<float4*>(Ws + k * 132 + n4) =
                *reinterpret_cast<const float4*>(W + (size_t)(k0 + k) * HIDD + n0 + n4);
        }
        __syncthreads();

#pragma unroll
        for (int k = 0; k < 16; k++) {
            float4 a0 = *reinterpret_cast<const float4*>(As + k * 132 + ty * 8);
            float4 a1 = *reinterpret_cast<const float4*>(As + k * 132 + ty * 8 + 4);
            float4 b0 = *reinterpret_cast<const float4*>(Ws + k * 132 + tx * 8);
            float4 b1 = *reinterpret_cast<const float4*>(Ws + k * 132 + tx * 8 + 4);
            unsigned long long av[8] = {
                pk2(a0.x, a0.x), pk2(a0.y, a0.y), pk2(a0.z, a0.z), pk2(a0.w, a0.w),
                pk2(a1.x, a1.x), pk2(a1.y, a1.y), pk2(a1.z, a1.z), pk2(a1.w, a1.w)};
            unsigned long long bv[4] = {
                pk2(b0.x, b0.y), pk2(b0.z, b0.w), pk2(b1.x, b1.y), pk2(b1.z, b1.w)};
#pragma unroll
            for (int i = 0; i < 8; i++)
#pragma unroll
                for (int j = 0; j < 4; j++)
                    acc[i][j] = ffma2(av[i], bv[j], acc[i][j]);
        }
        __syncthreads();
    }

    // epilogue: bias + relu
#pragma unroll
    for (int i = 0; i < 8; i++) {
        const int gm = m0 + ty * 8 + i;
        float* crow  = C + (size_t)gm * HIDD + n0 + tx * 8;
#pragma unroll
        for (int j = 0; j < 4; j++) {
            float2 v   = upk2(acc[i][j]);
            const int n = n0 + tx * 8 + 2 * j;
            v.x = fmaxf(v.x + bias[n],     0.f);
            v.y = fmaxf(v.y + bias[n + 1], 0.f);
            *reinterpret_cast<float2*>(crow + 2 * j) = v;
        }
    }
}

// ---------------------------------------------------------------------------
// params = H2[M,1024] @ W3[1024,64] + b3, then coupling + logdet.
// One CTA per 128 rows (grid covers M only) -> logdet update race-free.
// moff: masked-half offset (0 even layers, 32 odd).
// ---------------------------------------------------------------------------
__global__ __launch_bounds__(256, 1)
void gemm3_coupling_kernel(const float* __restrict__ A,    // H2
                           const float* __restrict__ W,    // [1024,64]
                           const float* __restrict__ bias, // [64]
                           float* __restrict__ z,          // [B,64]
                           float* __restrict__ logdet,     // [B]
                           int moff) {
    __shared__ float As[16 * 132];
    __shared__ float Ws[16 * 68];
    __shared__ float P [128 * 65];

    const int tid = threadIdx.x;
    const int tx  = tid & 7;    // 8 groups x 8 cols = 64
    const int ty  = tid >> 3;   // 32 groups x 4 rows = 128
    const int m0  = blockIdx.x * 128;

    unsigned long long acc[4][4];
#pragma unroll
    for (int i = 0; i < 4; i++)
#pragma unroll
        for (int j = 0; j < 4; j++) acc[i][j] = 0ull;

    for (int k0 = 0; k0 < HIDD; k0 += 16) {
#pragma unroll
        for (int l = 0; l < 2; l++) {
            int idx = tid + l * 256;
            int m   = idx >> 2;
            int kk  = (idx & 3) << 2;
            const float4 v = *reinterpret_cast<const float4*>(
                A + (size_t)(m0 + m) * HIDD + k0 + kk);
            As[(kk + 0) * 132 + m] = v.x;
            As[(kk + 1) * 132 + m] = v.y;
            As[(kk + 2) * 132 + m] = v.z;
            As[(kk + 3) * 132 + m] = v.w;
        }
        {   // W tile 16x64: one float4 per thread
            int k  = tid >> 4;          // 0..15
            int n4 = (tid & 15) << 2;   // 0..60
            *reinterpret_cast<float4*>(Ws + k * 68 + n4) =
                *reinterpret_cast<const float4*>(W + (size_t)(k0 + k) * 64 + n4);
        }
        __syncthreads();

#pragma unroll
        for (int k = 0; k < 16; k++) {
            float4 a0 = *reinterpret_cast<const float4*>(As + k * 132 + ty * 4);
            float4 b0 = *reinterpret_cast<const float4*>(Ws + k * 68 + tx * 8);
            float4 b1 = *reinterpret_cast<const float4*>(Ws + k * 68 + tx * 8 + 4);
            unsigned long long av[4] = {
                pk2(a0.x, a0.x), pk2(a0.y, a0.y), pk2(a0.z, a0.z), pk2(a0.w, a0.w)};
            unsigned long long bv[4] = {
                pk2(b0.x, b0.y), pk2(b0.z, b0.w), pk2(b1.x, b1.y), pk2(b1.z, b1.w)};
#pragma unroll
            for (int i = 0; i < 4; i++)
#pragma unroll
                for (int j = 0; j < 4; j++)
                    acc[i][j] = ffma2(av[i], bv[j], acc[i][j]);
        }
        __syncthreads();
    }

    // stage params into SMEM
#pragma unroll
    for (int i = 0; i < 4; i++) {
        const int r = ty * 4 + i;
#pragma unroll
        for (int j = 0; j < 4; j++) {
            float2 v  = upk2(acc[i][j]);
            const int n = tx * 8 + 2 * j;
            P[r * 65 + n]     = v.x + bias[n];
            P[r * 65 + n + 1] = v.y + bias[n + 1];
        }
    }
    __syncthreads();

    // coupling: one thread per row
    if (tid < 128) {
        const int gm = m0 + tid;
        float sum = 0.f;
        float* zrow = z + (size_t)gm * TDIM + moff;
#pragma unroll 8
        for (int j = 0; j < HALF_; j++) {
            float s = tanhf(P[tid * 65 + j]);
            float t = P[tid * 65 + HALF_ + j];
            zrow[j] = zrow[j] * expf(s) + t;
            sum += s;
        }
        logdet[gm] += sum;
    }
}

// ---------------------------------------------------------------------------
extern "C" void kernel_launch(void* const* d_in, const int* in_sizes, int n_in,
                              void* d_out, int out_size) {
    const float* T    = (const float*)d_in[0];
    const float* cond = (const float*)d_in[1];
    const float* W1   = (const float*)d_in[2];
    const float* b1   = (const float*)d_in[3];
    const float* W2   = (const float*)d_in[4];
    const float* b2   = (const float*)d_in[5];
    const float* W3   = (const float*)d_in[6];
    const float* b3   = (const float*)d_in[7];

    float* out    = (float*)d_out;
    float* z      = out;                          // [B,64]
    float* logdet = out + (size_t)BN_ * TDIM;     // [B]

    float *U, *H1, *H2;
    cudaGetSymbolAddress((void**)&U,  g_U);
    cudaGetSymbolAddress((void**)&H1, g_H1);
    cudaGetSymbolAddress((void**)&H2, g_H2);

    init_kernel<<<(BN_ * TDIM + 255) / 256, 256>>>(T, out);

    for (int i = 0; i < 6; i++) {
        const int uoff = (i % 2 == 0) ? HALF_ : 0;   // unmasked half offset
        const int moff = (i % 2 == 0) ? 0 : HALF_;   // masked half offset

        build_u_kernel<<<(BN_ * KIN + 255) / 256, 256>>>(z, cond, U, uoff);

        gemm_relu_kernel<<<dim3(HIDD / 128, BN_ / 128), 256>>>(
            U, KIN, KIN, W1 + (size_t)i * KIN * HIDD, b1 + (size_t)i * HIDD, H1);

        gemm_relu_kernel<<<dim3(HIDD / 128, BN_ / 128), 256>>>(
            H1, HIDD, HIDD, W2 + (size_t)i * HIDD * HIDD, b2 + (size_t)i * HIDD, H2);

        gemm3_coupling_kernel<<<BN_ / 128, 256>>>(
            H2, W3 + (size_t)i * HIDD * 64, b3 + (size_t)i * 64, z, logdet, moff);
    }
}

// round 13
// speedup vs baseline: 1.0005x; 1.0005x over previous
#include <cuda_runtime.h>
#include <math.h>

// ---------------------------------------------------------------------------
// ConditionalNormalizingFlow: L=6 RealNVP coupling layers.
//   B=32768, T_DIM=64 (HALF=32), COND=128, HID=1024.
// Per layer: params = MLP(concat(unmasked, cond)) ; s=tanh(p[:32]); t=p[32:]
//            z[masked] = z[masked]*exp(s) + t ; logdet += sum(s)
// Output: z [B,64] then log_det [B] (float32), concatenated in d_out.
// ---------------------------------------------------------------------------

#define BN_ 32768
#define TDIM 64
#define HALF_ 32
#define CONDD 128
#define HIDD 1024
#define KIN 160   // HALF + COND

// Scratch (device globals: allocation-free per harness rules)
__device__ float g_U [ (size_t)BN_ * KIN  ];   // 21 MB
__device__ float g_H1[ (size_t)BN_ * HIDD ];   // 128 MB
__device__ float g_H2[ (size_t)BN_ * HIDD ];   // 128 MB

// ---- packed f32x2 helpers (Blackwell FFMA2 path) --------------------------
__device__ __forceinline__ unsigned long long pk2(float x, float y) {
    unsigned long long r;
    asm("mov.b64 %0, {%1, %2};" : "=l"(r)
        : "r"(__float_as_uint(x)), "r"(__float_as_uint(y)));
    return r;
}
__device__ __forceinline__ float2 upk2(unsigned long long v) {
    unsigned int lo, hi;
    asm("mov.b64 {%0, %1}, %2;" : "=r"(lo), "=r"(hi) : "l"(v));
    return make_float2(__uint_as_float(lo), __uint_as_float(hi));
}
__device__ __forceinline__ unsigned long long ffma2(unsigned long long a,
                                                    unsigned long long b,
                                                    unsigned long long c) {
    unsigned long long d;
    asm("fma.rn.f32x2 %0, %1, %2, %3;" : "=l"(d) : "l"(a), "l"(b), "l"(c));
    return d;
}

// ---------------------------------------------------------------------------
// init: z = T, logdet = 0
// ---------------------------------------------------------------------------
__global__ void init_kernel(const float* __restrict__ T, float* __restrict__ out) {
    int i = blockIdx.x * 256 + threadIdx.x;
    if (i < BN_ * TDIM) out[i] = T[i];
    if (i < BN_)        out[(size_t)BN_ * TDIM + i] = 0.f;
}

// ---------------------------------------------------------------------------
// build U = concat(unmasked(z), cond)  -> [B, 160]
// uoff: offset of the unmasked half inside z row (32 for even layers, 0 odd)
// ---------------------------------------------------------------------------
__global__ void build_u_kernel(const float* __restrict__ z,
                               const float* __restrict__ cond,
                               float* __restrict__ U, int uoff) {
    int i = blockIdx.x * 256 + threadIdx.x;
    if (i >= BN_ * KIN) return;
    int b = i / KIN;
    int k = i - b * KIN;
    U[i] = (k < HALF_) ? z[(size_t)b * TDIM + uoff + k]
                       : cond[(size_t)b * CONDD + (k - HALF_)];
}

// ---------------------------------------------------------------------------
// C[M,1024] = relu(A[M,K] @ W[K,1024] + bias)     M=32768, K in {160,1024}
// Tiles: 128x128x16, 256 threads, 8x8 per-thread tile, f32x2 FMA.
// ---------------------------------------------------------------------------
__global__ __launch_bounds__(256, 2)
void gemm_relu_kernel(const float* __restrict__ A, int lda, int K,
                      const float* __restrict__ W,
                      const float* __restrict__ bias,
                      float* __restrict__ C) {
    __shared__ float As[16 * 132];
    __shared__ float Ws[16 * 132];

    const int tid = threadIdx.x;
    const int tx  = tid & 15;   // 16 groups x 8 cols = 128
    const int ty  = tid >> 4;   // 16 groups x 8 rows = 128
    const int m0  = blockIdx.y * 128;
    const int n0  = blockIdx.x * 128;

    unsigned long long acc[8][4];
#pragma unroll
    for (int i = 0; i < 8; i++)
#pragma unroll
        for (int j = 0; j < 4; j++) acc[i][j] = 0ull;

    for (int k0 = 0; k0 < K; k0 += 16) {
        // load A tile 128x16 (float4 along K, store transposed [k][m])
#pragma unroll
        for (int l = 0; l < 2; l++) {
            int idx = tid + l * 256;      // 0..511 float4 slots
            int m   = idx >> 2;           // 0..127
            int kk  = (idx & 3) << 2;     // 0,4,8,12
            const float4 v = *reinterpret_cast<const float4*>(
                A + (size_t)(m0 + m) * lda + k0 + kk);
            As[(kk + 0) * 132 + m] = v.x;
            As[(kk + 1) * 132 + m] = v.y;
            As[(kk + 2) * 132 + m] = v.z;
            As[(kk + 3) * 132 + m] = v.w;
        }
        // load W tile 16x128 (row-major, coalesced float4 along N)
#pragma unroll
        for (int l = 0; l < 2; l++) {
            int idx = tid + l * 256;
            int k   = idx >> 5;           // 0..15
            int n4  = (idx & 31) << 2;    // 0..124
            *reinterpret_cast<float4*>(Ws + k * 132 + n4) =
                *reinterpret_cast<const float4*>(W + (size_t)(k0 + k) * HIDD + n0 + n4);
        }
        __syncthreads();

#pragma unroll
        for (int k = 0; k < 16; k++) {
            float4 a0 = *reinterpret_cast<const float4*>(As + k * 132 + ty * 8);
            float4 a1 = *reinterpret_cast<const float4*>(As + k * 132 + ty * 8 + 4);
            float4 b0 = *reinterpret_cast<const float4*>(Ws + k * 132 + tx * 8);
            float4 b1 = *reinterpret_cast<const float4*>(Ws + k * 132 + tx * 8 + 4);
            unsigned long long av[8] = {
                pk2(a0.x, a0.x), pk2(a0.y, a0.y), pk2(a0.z, a0.z), pk2(a0.w, a0.w),
                pk2(a1.x, a1.x), pk2(a1.y, a1.y), pk2(a1.z, a1.z), pk2(a1.w, a1.w)};
            unsigned long long bv[4] = {
                pk2(b0.x, b0.y), pk2(b0.z, b0.w), pk2(b1.x, b1.y), pk2(b1.z, b1.w)};
#pragma unroll
            for (int i = 0; i < 8; i++)
#pragma unroll
                for (int j = 0; j < 4; j++)
                    acc[i][j] = ffma2(av[i], bv[j], acc[i][j]);
        }
        __syncthreads();
    }

    // epilogue: bias + relu
#pragma unroll
    for (int i = 0; i < 8; i++) {
        const int gm = m0 + ty * 8 + i;
        float* crow  = C + (size_t)gm * HIDD + n0 + tx * 8;
#pragma unroll
        for (int j = 0; j < 4; j++) {
            float2 v   = upk2(acc[i][j]);
            const int n = n0 + tx * 8 + 2 * j;
            v.x = fmaxf(v.x + bias[n],     0.f);
            v.y = fmaxf(v.y + bias[n + 1], 0.f);
            *reinterpret_cast<float2*>(crow + 2 * j) = v;
        }
    }
}

// ---------------------------------------------------------------------------
// params = H2[M,1024] @ W3[1024,64] + b3, then coupling + logdet.
// One CTA per 128 rows (grid covers M only) -> logdet update race-free.
// moff: masked-half offset (0 even layers, 32 odd).
// ---------------------------------------------------------------------------
__global__ __launch_bounds__(256, 1)
void gemm3_coupling_kernel(const float* __restrict__ A,    // H2
                           const float* __restrict__ W,    // [1024,64]
                           const float* __restrict__ bias, // [64]
                           float* __restrict__ z,          // [B,64]
                           float* __restrict__ logdet,     // [B]
                           int moff) {
    __shared__ float As[16 * 132];
    __shared__ float Ws[16 * 68];
    __shared__ float P [128 * 65];

    const int tid = threadIdx.x;
    const int tx  = tid & 7;    // 8 groups x 8 cols = 64
    const int ty  = tid >> 3;   // 32 groups x 4 rows = 128
    const int m0  = blockIdx.x * 128;

    unsigned long long acc[4][4];
#pragma unroll
    for (int i = 0; i < 4; i++)
#pragma unroll
        for (int j = 0; j < 4; j++) acc[i][j] = 0ull;

    for (int k0 = 0; k0 < HIDD; k0 += 16) {
#pragma unroll
        for (int l = 0; l < 2; l++) {
            int idx = tid + l * 256;
            int m   = idx >> 2;
            int kk  = (idx & 3) << 2;
            const float4 v = *reinterpret_cast<const float4*>(
                A + (size_t)(m0 + m) * HIDD + k0 + kk);
            As[(kk + 0) * 132 + m] = v.x;
            As[(kk + 1) * 132 + m] = v.y;
            As[(kk + 2) * 132 + m] = v.z;
            As[(kk + 3) * 132 + m] = v.w;
        }
        {   // W tile 16x64: one float4 per thread
            int k  = tid >> 4;          // 0..15
            int n4 = (tid & 15) << 2;   // 0..60
            *reinterpret_cast<float4*>(Ws + k * 68 + n4) =
                *reinterpret_cast<const float4*>(W + (size_t)(k0 + k) * 64 + n4);
        }
        __syncthreads();

#pragma unroll
        for (int k = 0; k < 16; k++) {
            float4 a0 = *reinterpret_cast<const float4*>(As + k * 132 + ty * 4);
            float4 b0 = *reinterpret_cast<const float4*>(Ws + k * 68 + tx * 8);
            float4 b1 = *reinterpret_cast<const float4*>(Ws + k * 68 + tx * 8 + 4);
            unsigned long long av[4] = {
                pk2(a0.x, a0.x), pk2(a0.y, a0.y), pk2(a0.z, a0.z), pk2(a0.w, a0.w)};
            unsigned long long bv[4] = {
                pk2(b0.x, b0.y), pk2(b0.z, b0.w), pk2(b1.x, b1.y), pk2(b1.z, b1.w)};
#pragma unroll
            for (int i = 0; i < 4; i++)
#pragma unroll
                for (int j = 0; j < 4; j++)
                    acc[i][j] = ffma2(av[i], bv[j], acc[i][j]);
        }
        __syncthreads();
    }

    // stage params into SMEM
#pragma unroll
    for (int i = 0; i < 4; i++) {
        const int r = ty * 4 + i;
#pragma unroll
        for (int j = 0; j < 4; j++) {
            float2 v  = upk2(acc[i][j]);
            const int n = tx * 8 + 2 * j;
            P[r * 65 + n]     = v.x + bias[n];
            P[r * 65 + n + 1] = v.y + bias[n + 1];
        }
    }
    __syncthreads();

    // coupling: one thread per row
    if (tid < 128) {
        const int gm = m0 + tid;
        float sum = 0.f;
        float* zrow = z + (size_t)gm * TDIM + moff;
#pragma unroll 8
        for (int j = 0; j < HALF_; j++) {
            float s = tanhf(P[tid * 65 + j]);
            float t = P[tid * 65 + HALF_ + j];
            zrow[j] = zrow[j] * expf(s) + t;
            sum += s;
        }
        logdet[gm] += sum;
    }
}

// ---------------------------------------------------------------------------
extern "C" void kernel_launch(void* const* d_in, const int* in_sizes, int n_in,
                              void* d_out, int out_size) {
    const float* T    = (const float*)d_in[0];
    const float* cond = (const float*)d_in[1];
    const float* W1   = (const float*)d_in[2];
    const float* b1   = (const float*)d_in[3];
    const float* W2   = (const float*)d_in[4];
    const float* b2   = (const float*)d_in[5];
    const float* W3   = (const float*)d_in[6];
    const float* b3   = (const float*)d_in[7];

    float* out    = (float*)d_out;
    float* z      = out;                          // [B,64]
    float* logdet = out + (size_t)BN_ * TDIM;     // [B]

    float *U, *H1, *H2;
    cudaGetSymbolAddress((void**)&U,  g_U);
    cudaGetSymbolAddress((void**)&H1, g_H1);
    cudaGetSymbolAddress((void**)&H2, g_H2);

    init_kernel<<<(BN_ * TDIM + 255) / 256, 256>>>(T, out);

    for (int i = 0; i < 6; i++) {
        const int uoff = (i % 2 == 0) ? HALF_ : 0;   // unmasked half offset
        const int moff = (i % 2 == 0) ? 0 : HALF_;   // masked half offset

        build_u_kernel<<<(BN_ * KIN + 255) / 256, 256>>>(z, cond, U, uoff);

        gemm_relu_kernel<<<dim3(HIDD / 128, BN_ / 128), 256>>>(
            U, KIN, KIN, W1 + (size_t)i * KIN * HIDD, b1 + (size_t)i * HIDD, H1);

        gemm_relu_kernel<<<dim3(HIDD / 128, BN_ / 128), 256>>>(
            H1, HIDD, HIDD, W2 + (size_t)i * HIDD * HIDD, b2 + (size_t)i * HIDD, H2);

        gemm3_coupling_kernel<<<BN_ / 128, 256>>>(
            H2, W3 + (size_t)i * HIDD * 64, b3 + (size_t)i * 64, z, logdet, moff);
    }
}

// round 14
// speedup vs baseline: 1.0011x; 1.0005x over previous
#include <cuda_runtime.h>
#include <math.h>

// ---------------------------------------------------------------------------
// ConditionalNormalizingFlow: L=6 RealNVP coupling layers.
//   B=32768, T_DIM=64 (HALF=32), COND=128, HID=1024.
// Per layer: params = MLP(concat(unmasked, cond)) ; s=tanh(p[:32]); t=p[32:]
//            z[masked] = z[masked]*exp(s) + t ; logdet += sum(s)
// Output: z [B,64] then log_det [B] (float32), concatenated in d_out.
// ---------------------------------------------------------------------------

#define BN_ 32768
#define TDIM 64
#define HALF_ 32
#define CONDD 128
#define HIDD 1024
#define KIN 160   // HALF + COND

// Scratch (device globals: allocation-free per harness rules)
__device__ float g_U [ (size_t)BN_ * KIN  ];   // 21 MB
__device__ float g_H1[ (size_t)BN_ * HIDD ];   // 128 MB
__device__ float g_H2[ (size_t)BN_ * HIDD ];   // 128 MB

// ---- packed f32x2 helpers (Blackwell FFMA2 path) --------------------------
__device__ __forceinline__ unsigned long long pk2(float x, float y) {
    unsigned long long r;
    asm("mov.b64 %0, {%1, %2};" : "=l"(r)
        : "r"(__float_as_uint(x)), "r"(__float_as_uint(y)));
    return r;
}
__device__ __forceinline__ float2 upk2(unsigned long long v) {
    unsigned int lo, hi;
    asm("mov.b64 {%0, %1}, %2;" : "=r"(lo), "=r"(hi) : "l"(v));
    return make_float2(__uint_as_float(lo), __uint_as_float(hi));
}
__device__ __forceinline__ unsigned long long ffma2(unsigned long long a,
                                                    unsigned long long b,
                                                    unsigned long long c) {
    unsigned long long d;
    asm("fma.rn.f32x2 %0, %1, %2, %3;" : "=l"(d) : "l"(a), "l"(b), "l"(c));
    return d;
}

// ---------------------------------------------------------------------------
// init: z = T, logdet = 0
// ---------------------------------------------------------------------------
__global__ void init_kernel(const float* __restrict__ T, float* __restrict__ out) {
    int i = blockIdx.x * 256 + threadIdx.x;
    if (i < BN_ * TDIM) out[i] = T[i];
    if (i < BN_)        out[(size_t)BN_ * TDIM + i] = 0.f;
}

// ---------------------------------------------------------------------------
// build U = concat(unmasked(z), cond)  -> [B, 160]
// uoff: offset of the unmasked half inside z row (32 for even layers, 0 odd)
// ---------------------------------------------------------------------------
__global__ void build_u_kernel(const float* __restrict__ z,
                               const float* __restrict__ cond,
                               float* __restrict__ U, int uoff) {
    int i = blockIdx.x * 256 + threadIdx.x;
    if (i >= BN_ * KIN) return;
    int b = i / KIN;
    int k = i - b * KIN;
    U[i] = (k < HALF_) ? z[(size_t)b * TDIM + uoff + k]
                       : cond[(size_t)b * CONDD + (k - HALF_)];
}

// ---------------------------------------------------------------------------
// C[M,1024] = relu(A[M,K] @ W[K,1024] + bias)     M=32768, K in {160,1024}
// Tiles: 128x128x16, 256 threads, 8x8 per-thread tile, f32x2 FMA.
// ---------------------------------------------------------------------------
__global__ __launch_bounds__(256, 2)
void gemm_relu_kernel(const float* __restrict__ A, int lda, int K,
                      const float* __restrict__ W,
                      const float* __restrict__ bias,
                      float* __restrict__ C) {
    __shared__ float As[16 * 132];
    __shared__ float Ws[16 * 132];

    const int tid = threadIdx.x;
    const int tx  = tid & 15;   // 16 groups x 8 cols = 128
    const int ty  = tid >> 4;   // 16 groups x 8 rows = 128
    const int m0  = blockIdx.y * 128;
    const int n0  = blockIdx.x * 128;

    unsigned long long acc[8][4];
#pragma unroll
    for (int i = 0; i < 8; i++)
#pragma unroll
        for (int j = 0; j < 4; j++) acc[i][j] = 0ull;

    for (int k0 = 0; k0 < K; k0 += 16) {
        // load A tile 128x16 (float4 along K, store transposed [k][m])
#pragma unroll
        for (int l = 0; l < 2; l++) {
            int idx = tid + l * 256;      // 0..511 float4 slots
            int m   = idx >> 2;           // 0..127
            int kk  = (idx & 3) << 2;     // 0,4,8,12
            const float4 v = *reinterpret_cast<const float4*>(
                A + (size_t)(m0 + m) * lda + k0 + kk);
            As[(kk + 0) * 132 + m] = v.x;
            As[(kk + 1) * 132 + m] = v.y;
            As[(kk + 2) * 132 + m] = v.z;
            As[(kk + 3) * 132 + m] = v.w;
        }
        // load W tile 16x128 (row-major, coalesced float4 along N)
#pragma unroll
        for (int l = 0; l < 2; l++) {
            int idx = tid + l * 256;
            int k   = idx >> 5;           // 0..15
            int n4  = (idx & 31) << 2;    // 0..124
            *reinterpret_cast<float4*>(Ws + k * 132 + n4) =
                *reinterpret_cast<const float4*>(W + (size_t)(k0 + k) * HIDD + n0 + n4);
        }
        __syncthreads();

#pragma unroll
        for (int k = 0; k < 16; k++) {
            float4 a0 = *reinterpret_cast<const float4*>(As + k * 132 + ty * 8);
            float4 a1 = *reinterpret_cast<const float4*>(As + k * 132 + ty * 8 + 4);
            float4 b0 = *reinterpret_cast<const float4*>(Ws + k * 132 + tx * 8);
            float4 b1 = *reinterpret_cast<const float4*>(Ws + k * 132 + tx * 8 + 4);
            unsigned long long av[8] = {
                pk2(a0.x, a0.x), pk2(a0.y, a0.y), pk2(a0.z, a0.z), pk2(a0.w, a0.w),
                pk2(a1.x, a1.x), pk2(a1.y, a1.y), pk2(a1.z, a1.z), pk2(a1.w, a1.w)};
            unsigned long long bv[4] = {
                pk2(b0.x, b0.y), pk2(b0.z, b0.w), pk2(b1.x, b1.y), pk2(b1.z, b1.w)};
#pragma unroll
            for (int i = 0; i < 8; i++)
#pragma unroll
                for (int j = 0; j < 4; j++)
                    acc[i][j] = ffma2(av[i], bv[j], acc[i][j]);
        }
        __syncthreads();
    }

    // epilogue: bias + relu
#pragma unroll
    for (int i = 0; i < 8; i++) {
        const int gm = m0 + ty * 8 + i;
        float* crow  = C + (size_t)gm * HIDD + n0 + tx * 8;
#pragma unroll
        for (int j = 0; j < 4; j++) {
            float2 v   = upk2(acc[i][j]);
            const int n = n0 + tx * 8 + 2 * j;
            v.x = fmaxf(v.x + bias[n],     0.f);
            v.y = fmaxf(v.y + bias[n + 1], 0.f);
            *reinterpret_cast<float2*>(crow + 2 * j) = v;
        }
    }
}

// ---------------------------------------------------------------------------
// params = H2[M,1024] @ W3[1024,64] + b3, then coupling + logdet.
// One CTA per 128 rows (grid covers M only) -> logdet update race-free.
// moff: masked-half offset (0 even layers, 32 odd).
// ---------------------------------------------------------------------------
__global__ __launch_bounds__(256, 1)
void gemm3_coupling_kernel(const float* __restrict__ A,    // H2
                           const float* __restrict__ W,    // [1024,64]
                           const float* __restrict__ bias, // [64]
                           float* __restrict__ z,          // [B,64]
                           float* __restrict__ logdet,     // [B]
                           int moff) {
    __shared__ float As[16 * 132];
    __shared__ float Ws[16 * 68];
    __shared__ float P [128 * 65];

    const int tid = threadIdx.x;
    const int tx  = tid & 7;    // 8 groups x 8 cols = 64
    const int ty  = tid >> 3;   // 32 groups x 4 rows = 128
    const int m0  = blockIdx.x * 128;

    unsigned long long acc[4][4];
#pragma unroll
    for (int i = 0; i < 4; i++)
#pragma unroll
        for (int j = 0; j < 4; j++) acc[i][j] = 0ull;

    for (int k0 = 0; k0 < HIDD; k0 += 16) {
#pragma unroll
        for (int l = 0; l < 2; l++) {
            int idx = tid + l * 256;
            int m   = idx >> 2;
            int kk  = (idx & 3) << 2;
            const float4 v = *reinterpret_cast<const float4*>(
                A + (size_t)(m0 + m) * HIDD + k0 + kk);
            As[(kk + 0) * 132 + m] = v.x;
            As[(kk + 1) * 132 + m] = v.y;
            As[(kk + 2) * 132 + m] = v.z;
            As[(kk + 3) * 132 + m] = v.w;
        }
        {   // W tile 16x64: one float4 per thread
            int k  = tid >> 4;          // 0..15
            int n4 = (tid & 15) << 2;   // 0..60
            *reinterpret_cast<float4*>(Ws + k * 68 + n4) =
                *reinterpret_cast<const float4*>(W + (size_t)(k0 + k) * 64 + n4);
        }
        __syncthreads();

#pragma unroll
        for (int k = 0; k < 16; k++) {
            float4 a0 = *reinterpret_cast<const float4*>(As + k * 132 + ty * 4);
            float4 b0 = *reinterpret_cast<const float4*>(Ws + k * 68 + tx * 8);
            float4 b1 = *reinterpret_cast<const float4*>(Ws + k * 68 + tx * 8 + 4);
            unsigned long long av[4] = {
                pk2(a0.x, a0.x), pk2(a0.y, a0.y), pk2(a0.z, a0.z), pk2(a0.w, a0.w)};
            unsigned long long bv[4] = {
                pk2(b0.x, b0.y), pk2(b0.z, b0.w), pk2(b1.x, b1.y), pk2(b1.z, b1.w)};
#pragma unroll
            for (int i = 0; i < 4; i++)
#pragma unroll
                for (int j = 0; j < 4; j++)
                    acc[i][j] = ffma2(av[i], bv[j], acc[i][j]);
        }
        __syncthreads();
    }

    // stage params into SMEM
#pragma unroll
    for (int i = 0; i < 4; i++) {
        const int r = ty * 4 + i;
#pragma unroll
        for (int j = 0; j < 4; j++) {
            float2 v  = upk2(acc[i][j]);
            const int n = tx * 8 + 2 * j;
            P[r * 65 + n]     = v.x + bias[n];
            P[r * 65 + n + 1] = v.y + bias[n + 1];
        }
    }
    __syncthreads();

    // coupling: one thread per row
    if (tid < 128) {
        const int gm = m0 + tid;
        float sum = 0.f;
        float* zrow = z + (size_t)gm * TDIM + moff;
#pragma unroll 8
        for (int j = 0; j < HALF_; j++) {
            float s = tanhf(P[tid * 65 + j]);
            float t = P[tid * 65 + HALF_ + j];
            zrow[j] = zrow[j] * expf(s) + t;
            sum += s;
        }
        logdet[gm] += sum;
    }
}

// ---------------------------------------------------------------------------
extern "C" void kernel_launch(void* const* d_in, const int* in_sizes, int n_in,
                              void* d_out, int out_size) {
    const float* T    = (const float*)d_in[0];
    const float* cond = (const float*)d_in[1];
    const float* W1   = (const float*)d_in[2];
    const float* b1   = (const float*)d_in[3];
    const float* W2   = (const float*)d_in[4];
    const float* b2   = (const float*)d_in[5];
    const float* W3   = (const float*)d_in[6];
    const float* b3   = (const float*)d_in[7];

    float* out    = (float*)d_out;
    float* z      = out;                          // [B,64]
    float* logdet = out + (size_t)BN_ * TDIM;     // [B]

    float *U, *H1, *H2;
    cudaGetSymbolAddress((void**)&U,  g_U);
    cudaGetSymbolAddress((void**)&H1, g_H1);
    cudaGetSymbolAddress((void**)&H2, g_H2);

    init_kernel<<<(BN_ * TDIM + 255) / 256, 256>>>(T, out);

    for (int i = 0; i < 6; i++) {
        const int uoff = (i % 2 == 0) ? HALF_ : 0;   // unmasked half offset
        const int moff = (i % 2 == 0) ? 0 : HALF_;   // masked half offset

        build_u_kernel<<<(BN_ * KIN + 255) / 256, 256>>>(z, cond, U, uoff);

        gemm_relu_kernel<<<dim3(HIDD / 128, BN_ / 128), 256>>>(
            U, KIN, KIN, W1 + (size_t)i * KIN * HIDD, b1 + (size_t)i * HIDD, H1);

        gemm_relu_kernel<<<dim3(HIDD / 128, BN_ / 128), 256>>>(
            H1, HIDD, HIDD, W2 + (size_t)i * HIDD * HIDD, b2 + (size_t)i * HIDD, H2);

        gemm3_coupling_kernel<<<BN_ / 128, 256>>>(
            H2, W3 + (size_t)i * HIDD * 64, b3 + (size_t)i * 64, z, logdet, moff);
    }
}

// round 15
// speedup vs baseline: 1.0016x; 1.0005x over previous
#include <cuda_runtime.h>
#include <math.h>

// ---------------------------------------------------------------------------
// ConditionalNormalizingFlow: L=6 RealNVP coupling layers.
//   B=32768, T_DIM=64 (HALF=32), COND=128, HID=1024.
// Per layer: params = MLP(concat(unmasked, cond)) ; s=tanh(p[:32]); t=p[32:]
//            z[masked] = z[masked]*exp(s) + t ; logdet += sum(s)
// Output: z [B,64] then log_det [B] (float32), concatenated in d_out.
// ---------------------------------------------------------------------------

#define BN_ 32768
#define TDIM 64
#define HALF_ 32
#define CONDD 128
#define HIDD 1024
#define KIN 160   // HALF + COND

// Scratch (device globals: allocation-free per harness rules)
__device__ float g_U [ (size_t)BN_ * KIN  ];   // 21 MB
__device__ float g_H1[ (size_t)BN_ * HIDD ];   // 128 MB
__device__ float g_H2[ (size_t)BN_ * HIDD ];   // 128 MB

// ---- packed f32x2 helpers (Blackwell FFMA2 path) --------------------------
__device__ __forceinline__ unsigned long long pk2(float x, float y) {
    unsigned long long r;
    asm("mov.b64 %0, {%1, %2};" : "=l"(r)
        : "r"(__float_as_uint(x)), "r"(__float_as_uint(y)));
    return r;
}
__device__ __forceinline__ float2 upk2(unsigned long long v) {
    unsigned int lo, hi;
    asm("mov.b64 {%0, %1}, %2;" : "=r"(lo), "=r"(hi) : "l"(v));
    return make_float2(__uint_as_float(lo), __uint_as_float(hi));
}
__device__ __forceinline__ unsigned long long ffma2(unsigned long long a,
                                                    unsigned long long b,
                                                    unsigned long long c) {
    unsigned long long d;
    asm("fma.rn.f32x2 %0, %1, %2, %3;" : "=l"(d) : "l"(a), "l"(b), "l"(c));
    return d;
}

// ---------------------------------------------------------------------------
// init: z = T, logdet = 0
// ---------------------------------------------------------------------------
__global__ void init_kernel(const float* __restrict__ T, float* __restrict__ out) {
    int i = blockIdx.x * 256 + threadIdx.x;
    if (i < BN_ * TDIM) out[i] = T[i];
    if (i < BN_)        out[(size_t)BN_ * TDIM + i] = 0.f;
}

// ---------------------------------------------------------------------------
// build U = concat(unmasked(z), cond)  -> [B, 160]
// uoff: offset of the unmasked half inside z row (32 for even layers, 0 odd)
// ---------------------------------------------------------------------------
__global__ void build_u_kernel(const float* __restrict__ z,
                               const float* __restrict__ cond,
                               float* __restrict__ U, int uoff) {
    int i = blockIdx.x * 256 + threadIdx.x;
    if (i >= BN_ * KIN) return;
    int b = i / KIN;
    int k = i - b * KIN;
    U[i] = (k < HALF_) ? z[(size_t)b * TDIM + uoff + k]
                       : cond[(size_t)b * CONDD + (k - HALF_)];
}

// ---------------------------------------------------------------------------
// C[M,1024] = relu(A[M,K] @ W[K,1024] + bias)     M=32768, K in {160,1024}
// Tiles: 128x128x16, 256 threads, 8x8 per-thread tile, f32x2 FMA.
// ---------------------------------------------------------------------------
__global__ __launch_bounds__(256, 2)
void gemm_relu_kernel(const float* __restrict__ A, int lda, int K,
                      const float* __restrict__ W,
                      const float* __restrict__ bias,
                      float* __restrict__ C) {
    __shared__ float As[16 * 132];
    __shared__ float Ws[16 * 132];

    const int tid = threadIdx.x;
    const int tx  = tid & 15;   // 16 groups x 8 cols = 128
    const int ty  = tid >> 4;   // 16 groups x 8 rows = 128
    const int m0  = blockIdx.y * 128;
    const int n0  = blockIdx.x * 128;

    unsigned long long acc[8][4];
#pragma unroll
    for (int i = 0; i < 8; i++)
#pragma unroll
        for (int j = 0; j < 4; j++) acc[i][j] = 0ull;

    for (int k0 = 0; k0 < K; k0 += 16) {
        // load A tile 128x16 (float4 along K, store transposed [k][m])
#pragma unroll
        for (int l = 0; l < 2; l++) {
            int idx = tid + l * 256;      // 0..511 float4 slots
            int m   = idx >> 2;           // 0..127
            int kk  = (idx & 3) << 2;     // 0,4,8,12
            const float4 v = *reinterpret_cast<const float4*>(
                A + (size_t)(m0 + m) * lda + k0 + kk);
            As[(kk + 0) * 132 + m] = v.x;
            As[(kk + 1) * 132 + m] = v.y;
            As[(kk + 2) * 132 + m] = v.z;
            As[(kk + 3) * 132 + m] = v.w;
        }
        // load W tile 16x128 (row-major, coalesced float4 along N)
#pragma unroll
        for (int l = 0; l < 2; l++) {
            int idx = tid + l * 256;
            int k   = idx >> 5;           // 0..15
            int n4  = (idx & 31) << 2;    // 0..124
            *reinterpret_cast<float4*>(Ws + k * 132 + n4) =
                *reinterpret_cast<const float4*>(W + (size_t)(k0 + k) * HIDD + n0 + n4);
        }
        __syncthreads();

#pragma unroll
        for (int k = 0; k < 16; k++) {
            float4 a0 = *reinterpret_cast<const float4*>(As + k * 132 + ty * 8);
            float4 a1 = *reinterpret_cast<const float4*>(As + k * 132 + ty * 8 + 4);
            float4 b0 = *reinterpret_cast<const float4*>(Ws + k * 132 + tx * 8);
            float4 b1 = *reinterpret_cast<const float4*>(Ws + k * 132 + tx * 8 + 4);
            unsigned long long av[8] = {
                pk2(a0.x, a0.x), pk2(a0.y, a0.y), pk2(a0.z, a0.z), pk2(a0.w, a0.w),
                pk2(a1.x, a1.x), pk2(a1.y, a1.y), pk2(a1.z, a1.z), pk2(a1.w, a1.w)};
            unsigned long long bv[4] = {
                pk2(b0.x, b0.y), pk2(b0.z, b0.w), pk2(b1.x, b1.y), pk2(b1.z, b1.w)};
#pragma unroll
            for (int i = 0; i < 8; i++)
#pragma unroll
                for (int j = 0; j < 4; j++)
                    acc[i][j] = ffma2(av[i], bv[j], acc[i][j]);
        }
        __syncthreads();
    }

    // epilogue: bias + relu
#pragma unroll
    for (int i = 0; i < 8; i++) {
        const int gm = m0 + ty * 8 + i;
        float* crow  = C + (size_t)gm * HIDD + n0 + tx * 8;
#pragma unroll
        for (int j = 0; j < 4; j++) {
            float2 v   = upk2(acc[i][j]);
            const int n = n0 + tx * 8 + 2 * j;
            v.x = fmaxf(v.x + bias[n],     0.f);
            v.y = fmaxf(v.y + bias[n + 1], 0.f);
            *reinterpret_cast<float2*>(crow + 2 * j) = v;
        }
    }
}

// ---------------------------------------------------------------------------
// params = H2[M,1024] @ W3[1024,64] + b3, then coupling + logdet.
// One CTA per 128 rows (grid covers M only) -> logdet update race-free.
// moff: masked-half offset (0 even layers, 32 odd).
// ---------------------------------------------------------------------------
__global__ __launch_bounds__(256, 1)
void gemm3_coupling_kernel(const float* __restrict__ A,    // H2
                           const float* __restrict__ W,    // [1024,64]
                           const float* __restrict__ bias, // [64]
                           float* __restrict__ z,          // [B,64]
                           float* __restrict__ logdet,     // [B]
                           int moff) {
    __shared__ float As[16 * 132];
    __shared__ float Ws[16 * 68];
    __shared__ float P [128 * 65];

    const int tid = threadIdx.x;
    const int tx  = tid & 7;    // 8 groups x 8 cols = 64
    const int ty  = tid >> 3;   // 32 groups x 4 rows = 128
    const int m0  = blockIdx.x * 128;

    unsigned long long acc[4][4];
#pragma unroll
    for (int i = 0; i < 4; i++)
#pragma unroll
        for (int j = 0; j < 4; j++) acc[i][j] = 0ull;

    for (int k0 = 0; k0 < HIDD; k0 += 16) {
#pragma unroll
        for (int l = 0; l < 2; l++) {
            int idx = tid + l * 256;
            int m   = idx >> 2;
            int kk  = (idx & 3) << 2;
            const float4 v = *reinterpret_cast<const float4*>(
                A + (size_t)(m0 + m) * HIDD + k0 + kk);
            As[(kk + 0) * 132 + m] = v.x;
            As[(kk + 1) * 132 + m] = v.y;
            As[(kk + 2) * 132 + m] = v.z;
            As[(kk + 3) * 132 + m] = v.w;
        }
        {   // W tile 16x64: one float4 per thread
            int k  = tid >> 4;          // 0..15
            int n4 = (tid & 15) << 2;   // 0..60
            *reinterpret_cast<float4*>(Ws + k * 68 + n4) =
                *reinterpret_cast<const float4*>(W + (size_t)(k0 + k) * 64 + n4);
        }
        __syncthreads();

#pragma unroll
        for (int k = 0; k < 16; k++) {
            float4 a0 = *reinterpret_cast<const float4*>(As + k * 132 + ty * 4);
            float4 b0 = *reinterpret_cast<const float4*>(Ws + k * 68 + tx * 8);
            float4 b1 = *reinterpret_cast<const float4*>(Ws + k * 68 + tx * 8 + 4);
            unsigned long long av[4] = {
                pk2(a0.x, a0.x), pk2(a0.y, a0.y), pk2(a0.z, a0.z), pk2(a0.w, a0.w)};
            unsigned long long bv[4] = {
                pk2(b0.x, b0.y), pk2(b0.z, b0.w), pk2(b1.x, b1.y), pk2(b1.z, b1.w)};
#pragma unroll
            for (int i = 0; i < 4; i++)
#pragma unroll
                for (int j = 0; j < 4; j++)
                    acc[i][j] = ffma2(av[i], bv[j], acc[i][j]);
        }
        __syncthreads();
    }

    // stage params into SMEM
#pragma unroll
    for (int i = 0; i < 4; i++) {
        const int r = ty * 4 + i;
#pragma unroll
        for (int j = 0; j < 4; j++) {
            float2 v  = upk2(acc[i][j]);
            const int n = tx * 8 + 2 * j;
            P[r * 65 + n]     = v.x + bias[n];
            P[r * 65 + n + 1] = v.y + bias[n + 1];
        }
    }
    __syncthreads();

    // coupling: one thread per row
    if (tid < 128) {
        const int gm = m0 + tid;
        float sum = 0.f;
        float* zrow = z + (size_t)gm * TDIM + moff;
#pragma unroll 8
        for (int j = 0; j < HALF_; j++) {
            float s = tanhf(P[tid * 65 + j]);
            float t = P[tid * 65 + HALF_ + j];
            zrow[j] = zrow[j] * expf(s) + t;
            sum += s;
        }
        logdet[gm] += sum;
    }
}

// ---------------------------------------------------------------------------
extern "C" void kernel_launch(void* const* d_in, const int* in_sizes, int n_in,
                              void* d_out, int out_size) {
    const float* T    = (const float*)d_in[0];
    const float* cond = (const float*)d_in[1];
    const float* W1   = (const float*)d_in[2];
    const float* b1   = (const float*)d_in[3];
    const float* W2   = (const float*)d_in[4];
    const float* b2   = (const float*)d_in[5];
    const float* W3   = (const float*)d_in[6];
    const float* b3   = (const float*)d_in[7];

    float* out    = (float*)d_out;
    float* z      = out;                          // [B,64]
    float* logdet = out + (size_t)BN_ * TDIM;     // [B]

    float *U, *H1, *H2;
    cudaGetSymbolAddress((void**)&U,  g_U);
    cudaGetSymbolAddress((void**)&H1, g_H1);
    cudaGetSymbolAddress((void**)&H2, g_H2);

    init_kernel<<<(BN_ * TDIM + 255) / 256, 256>>>(T, out);

    for (int i = 0; i < 6; i++) {
        const int uoff = (i % 2 == 0) ? HALF_ : 0;   // unmasked half offset
        const int moff = (i % 2 == 0) ? 0 : HALF_;   // masked half offset

        build_u_kernel<<<(BN_ * KIN + 255) / 256, 256>>>(z, cond, U, uoff);

        gemm_relu_kernel<<<dim3(HIDD / 128, BN_ / 128), 256>>>(
            U, KIN, KIN, W1 + (size_t)i * KIN * HIDD, b1 + (size_t)i * HIDD, H1);

        gemm_relu_kernel<<<dim3(HIDD / 128, BN_ / 128), 256>>>(
            H1, HIDD, HIDD, W2 + (size_t)i * HIDD * HIDD, b2 + (size_t)i * HIDD, H2);

        gemm3_coupling_kernel<<<BN_ / 128, 256>>>(
            H2, W3 + (size_t)i * HIDD * 64, b3 + (size_t)i * 64, z, logdet, moff);
    }
}